// round 3
// baseline (speedup 1.0000x reference)
#include <cuda_runtime.h>
#include <stdint.h>

// Problem shapes (fixed by the dataset)
#define MQ   1024       // queries
#define NDB  4096       // database rows
#define FD   128        // feature dim
#define TT   64         // time steps in x
#define TPOSE 64
#define PPOSE 96
#define POSE_ROW (TPOSE*PPOSE)      // 6144
#define OUT_GATHER (MQ*POSE_ROW)    // 6291456

#define NSPLIT 16       // n-splits for score kernel
#define MT 64           // m per score block
#define NPB (NDB/NSPLIT) // 256 n per block
#define NCHUNK 128      // n per smem chunk

// Scratch (device globals — no allocation allowed)
__device__ float g_qt[FD*MQ];          // q transposed: [f][m]
__device__ float g_sumA[NDB];          // ||a_n||^2
__device__ float g_candVal[MQ*NSPLIT];
__device__ int   g_candIdx[MQ*NSPLIT];

// ---------------------------------------------------------------------------
// packed f32x2 helpers (sm_100 packed fp32 pipe: 2x FFMA throughput)
// ---------------------------------------------------------------------------
__device__ __forceinline__ unsigned long long fma2(unsigned long long a,
                                                   unsigned long long b,
                                                   unsigned long long c) {
    unsigned long long d;
    asm("fma.rn.f32x2 %0, %1, %2, %3;" : "=l"(d) : "l"(a), "l"(b), "l"(c));
    return d;
}
__device__ __forceinline__ unsigned long long dup2(float v) {
    unsigned long long d;
    asm("mov.b64 %0, {%1, %1};" : "=l"(d) : "f"(v));
    return d;
}
__device__ __forceinline__ float2 unpack2(unsigned long long v) {
    float2 r;
    asm("mov.b64 {%0, %1}, %2;" : "=f"(r.x), "=f"(r.y) : "l"(v));
    return r;
}

// ---------------------------------------------------------------------------
// Kernel A: q[m][f] = mean_t x[m][t][f], written transposed as g_qt[f][m].
// 8 m per block, grid 128. Coalesced reads, smem transpose for coalesced write.
// ---------------------------------------------------------------------------
__global__ void qmean_kernel(const float* __restrict__ x) {
    __shared__ float sq[FD*9];    // [f][ml], stride 9 kills bank conflicts
    int tid = threadIdx.x;
    int m0 = blockIdx.x * 8;

    for (int pos = tid; pos < 8*FD; pos += 256) {
        int ml = pos >> 7;        // pos / 128
        int f  = pos & 127;
        const float* px = x + ((size_t)(m0 + ml) * TT) * FD + f;
        float s0 = 0.f, s1 = 0.f, s2 = 0.f, s3 = 0.f;
        #pragma unroll
        for (int t = 0; t < TT; t += 4) {
            s0 += px[(t+0)*FD];
            s1 += px[(t+1)*FD];
            s2 += px[(t+2)*FD];
            s3 += px[(t+3)*FD];
        }
        sq[f*9 + ml] = (s0 + s1 + s2 + s3) * (1.0f / 64.0f);
    }
    __syncthreads();
    for (int pos = tid; pos < 8*FD; pos += 256) {
        int f = pos >> 3, ml = pos & 7;
        g_qt[f*MQ + m0 + ml] = sq[f*9 + ml];
    }
}

// ---------------------------------------------------------------------------
// Kernel B: g_sumA[n] = sum_f audio[n][f]^2. Warp per row.
// ---------------------------------------------------------------------------
__global__ void sumsq_kernel(const float* __restrict__ audio) {
    int gw = (blockIdx.x * blockDim.x + threadIdx.x) >> 5;
    int lane = threadIdx.x & 31;
    for (int n = gw; n < NDB; n += 512) {   // grid 64 x 256 = 512 warps
        float4 v = *(const float4*)&audio[(size_t)n * FD + lane * 4];
        float s = v.x*v.x + v.y*v.y + v.z*v.z + v.w*v.w;
        #pragma unroll
        for (int off = 16; off > 0; off >>= 1)
            s += __shfl_down_sync(0xffffffffu, s, off);
        if (lane == 0) g_sumA[n] = s;
    }
}

// ---------------------------------------------------------------------------
// Kernel C: fused score + partial argmin.
// Grid (NSPLIT=16, MQ/MT=16), 256 threads.
// Block tile: 64 m x 256 n (2 chunks of 128 n). Thread tile: 4 m x 8 n,
// n packed in pairs for fma.rn.f32x2.
// Smem (dynamic, 96.5 KB): Qs[128][64] + As[128][128] (swizzled) + Ss[128].
// score(n,m) = ||a_n||^2 - 2 a_n.q_m  (same ordering as reference mse)
// ---------------------------------------------------------------------------
__global__ void __launch_bounds__(256, 2) score_kernel(const float* __restrict__ audio) {
    extern __shared__ float smem[];
    float* Qs = smem;                    // 8192 floats  [k][m]
    float* As = smem + 8192;             // 16384 floats [k][n^swz]
    float* Ss = smem + 8192 + 16384;     // 128 floats

    int tid = threadIdx.x;
    int tn = tid & 15;        // 16 threads over n (8 n each)
    int tm = tid >> 4;        // 16 thread-groups over m (4 m each)
    int m_base  = blockIdx.y * MT;
    int n_base0 = blockIdx.x * NPB;
    int c0 = tn * 4;

    // Load Qs: g_qt[f][m_base..m_base+63]  (coalesced, conflict-free store)
    for (int i = tid; i < FD*MT; i += 256) {
        int f = i >> 6, j = i & 63;
        Qs[i] = g_qt[f*MQ + m_base + j];
    }

    float bestV[4] = {3.4e38f, 3.4e38f, 3.4e38f, 3.4e38f};
    int   bestI[4] = {0, 0, 0, 0};

    for (int ch = 0; ch < NPB/NCHUNK; ++ch) {
        int nb = n_base0 + ch * NCHUNK;
        __syncthreads();   // protect As/Ss from prior-chunk readers

        // Transpose-load audio chunk: As[k][n ^ swz(k)] = audio[nb+n][k]
        // swz(k) = ((k>>2)&7)<<2  -> conflict-free LDS.128 reads, 4-way STS.
        for (int i = tid; i < NCHUNK*32; i += 256) {
            int k4 = i & 31, n = i >> 5;
            float4 v = *(const float4*)&audio[(size_t)(nb + n) * FD + k4 * 4];
            int col = n ^ ((k4 & 7) << 2);
            int r = (k4 * 4) * NCHUNK + col;
            As[r]       = v.x;
            As[r + 128] = v.y;
            As[r + 256] = v.z;
            As[r + 384] = v.w;
        }
        if (tid < NCHUNK) Ss[tid] = g_sumA[nb + tid];
        __syncthreads();

        // acc[mi][pj]: packed (n, n+1) fp32 pairs
        unsigned long long acc[4][4];
        #pragma unroll
        for (int a = 0; a < 4; ++a)
            #pragma unroll
            for (int b = 0; b < 4; ++b) acc[a][b] = 0ull;

        #pragma unroll 4
        for (int k = 0; k < FD; ++k) {
            int swz = ((k >> 2) & 7) << 2;
            const float* rowA = As + k * NCHUNK;
            int p0 = c0 ^ swz;
            ulonglong2 A0 = *(const ulonglong2*)(rowA + p0);        // n = c0..c0+3
            ulonglong2 A1 = *(const ulonglong2*)(rowA + p0 + 64);   // n = 64+c0..
            float4 qv = *(const float4*)(Qs + k * MT + tm * 4);
            unsigned long long q0 = dup2(qv.x), q1 = dup2(qv.y),
                               q2 = dup2(qv.z), q3 = dup2(qv.w);
            acc[0][0] = fma2(A0.x, q0, acc[0][0]);
            acc[0][1] = fma2(A0.y, q0, acc[0][1]);
            acc[0][2] = fma2(A1.x, q0, acc[0][2]);
            acc[0][3] = fma2(A1.y, q0, acc[0][3]);
            acc[1][0] = fma2(A0.x, q1, acc[1][0]);
            acc[1][1] = fma2(A0.y, q1, acc[1][1]);
            acc[1][2] = fma2(A1.x, q1, acc[1][2]);
            acc[1][3] = fma2(A1.y, q1, acc[1][3]);
            acc[2][0] = fma2(A0.x, q2, acc[2][0]);
            acc[2][1] = fma2(A0.y, q2, acc[2][1]);
            acc[2][2] = fma2(A1.x, q2, acc[2][2]);
            acc[2][3] = fma2(A1.y, q2, acc[2][3]);
            acc[3][0] = fma2(A0.x, q3, acc[3][0]);
            acc[3][1] = fma2(A0.y, q3, acc[3][1]);
            acc[3][2] = fma2(A1.x, q3, acc[3][2]);
            acc[3][3] = fma2(A1.y, q3, acc[3][3]);
        }

        // Epilogue: score = sumA - 2*dot; running per-thread argmin
        #pragma unroll
        for (int mi = 0; mi < 4; ++mi) {
            #pragma unroll
            for (int pj = 0; pj < 4; ++pj) {
                float2 d = unpack2(acc[mi][pj]);
                int nloc = (pj < 2) ? (c0 + pj * 2) : (64 + c0 + (pj - 2) * 2);
                float s0 = Ss[nloc]     - 2.0f * d.x;
                float s1 = Ss[nloc + 1] - 2.0f * d.y;
                int n0 = nb + nloc;
                if (s0 < bestV[mi]) { bestV[mi] = s0; bestI[mi] = n0; }
                if (s1 < bestV[mi]) { bestV[mi] = s1; bestI[mi] = n0 + 1; }
            }
        }
    }

    // Reduce over the 16 tn-lanes (same-tm threads are contiguous 16-lane groups)
    #pragma unroll
    for (int mi = 0; mi < 4; ++mi) {
        float v = bestV[mi]; int ix = bestI[mi];
        #pragma unroll
        for (int off = 8; off > 0; off >>= 1) {
            float ov = __shfl_down_sync(0xffffffffu, v, off, 16);
            int   oi = __shfl_down_sync(0xffffffffu, ix, off, 16);
            if (ov < v || (ov == v && oi < ix)) { v = ov; ix = oi; }
        }
        if (tn == 0) {
            int m = m_base + tm * 4 + mi;
            g_candVal[m * NSPLIT + blockIdx.x] = v;
            g_candIdx[m * NSPLIT + blockIdx.x] = ix;
        }
    }
}

// ---------------------------------------------------------------------------
// Kernel D: final argmin over NSPLIT candidates + pose row gather (+ loss).
// Block per m. Tie-break toward lower n matches jnp.argmin (first occurrence).
// ---------------------------------------------------------------------------
__global__ void gather_kernel(const float* __restrict__ pose,
                              const float* __restrict__ dummy,
                              float* __restrict__ out,
                              int extra, int dn) {
    int m = blockIdx.x;
    __shared__ int s_idx;
    if (threadIdx.x == 0) {
        float bv = 3.4e38f; int bi = 0;
        #pragma unroll
        for (int s = 0; s < NSPLIT; ++s) {
            float v = g_candVal[m * NSPLIT + s];
            int   i = g_candIdx[m * NSPLIT + s];
            if (v < bv || (v == bv && i < bi)) { bv = v; bi = i; }
        }
        s_idx = bi;
    }
    __syncthreads();
    int idx = s_idx;
    const float4* src = (const float4*)&pose[(size_t)idx * POSE_ROW];
    float4*       dst = (float4*)&out[(size_t)m * POSE_ROW];
    #pragma unroll
    for (int i = threadIdx.x; i < POSE_ROW / 4; i += 256) dst[i] = src[i];

    if (m == 0 && threadIdx.x == 0 && extra > 0) {
        float l = 0.f;
        for (int i = 0; i < dn; ++i) l += dummy[i];
        for (int e = 0; e < extra; ++e) out[OUT_GATHER + e] = l;
    }
}

// ---------------------------------------------------------------------------
// Launch. Inputs: [0]=x (M,T,F), [1]=y, [2]=audio (N,F), [3]=pose (N,Tp,P),
// [4]=dummy. Output: pose gather (M,Tp,P) [+ loss scalar if out_size allows].
// ---------------------------------------------------------------------------
extern "C" void kernel_launch(void* const* d_in, const int* in_sizes, int n_in,
                              void* d_out, int out_size) {
    const float* x     = (const float*)d_in[0];
    const float* audio = (const float*)d_in[2];
    const float* pose  = (const float*)d_in[3];
    const float* dummy = (const float*)d_in[4];
    float* out = (float*)d_out;

    const int smemC = (8192 + 16384 + 128) * (int)sizeof(float);  // 98816 B
    cudaFuncSetAttribute(score_kernel,
                         cudaFuncAttributeMaxDynamicSharedMemorySize, smemC);

    qmean_kernel<<<128, 256>>>(x);
    sumsq_kernel<<<64, 256>>>(audio);
    score_kernel<<<dim3(NSPLIT, MQ / MT), 256, smemC>>>(audio);

    int extra = out_size - OUT_GATHER;
    int dn = (n_in > 4) ? in_sizes[4] : 1;
    gather_kernel<<<MQ, 256>>>(pose, dummy, out, extra, dn);
}